// round 4
// baseline (speedup 1.0000x reference)
#include <cuda_runtime.h>
#include <math.h>

#define B_   32
#define T_   64
#define BT   2048            // B*T
#define IND  4894
#define E_   128
#define G3   384             // 3*H
#define NG   768             // both GRUs' gates

// ---------------- device scratch (no allocations allowed) ----------------
__device__ float g_emb[BT * E_];       // emb[m][e], m = b*T + t
__device__ float g_GI [BT * NG];       // precomputed input gates (both GRUs) + bih
__device__ float g_WhhT[E_ * NG];      // [kk][c], c = [Whh_a cols | Whh_b cols]
__device__ float g_WbetaT[E_ * E_];    // [kk][e]

// ---------------- K1: embedding GEMM  emb = x @ W_emb^T ----------------
// M=2048, N=128, K=4894. BM=16, 256 threads, each thread 2m x 4n.
__global__ void __launch_bounds__(256) k_embed(const float* __restrict__ x,
                                               const float* __restrict__ Wemb) {
    __shared__ float As[32][16];    // [kk][m]
    __shared__ float Bs[32][132];   // [kk][e], padded row
    const int m0  = blockIdx.x * 16;
    const int tid = threadIdx.x;
    const int tx  = tid & 31;   // n = tx*4 + nn
    const int ty  = tid >> 5;   // m = ty*2 + mm
    float acc[2][4];
#pragma unroll
    for (int a = 0; a < 2; a++)
#pragma unroll
        for (int b = 0; b < 4; b++) acc[a][b] = 0.f;

    for (int k0 = 0; k0 < IND; k0 += 32) {
        for (int l = tid; l < 16 * 32; l += 256) {
            int kk = l & 31, mm = l >> 5;
            int k = k0 + kk;
            As[kk][mm] = (k < IND) ? x[(m0 + mm) * IND + k] : 0.f;
        }
        for (int l = tid; l < 128 * 32; l += 256) {
            int kk = l & 31, e = l >> 5;
            int k = k0 + kk;
            Bs[kk][e] = (k < IND) ? Wemb[e * IND + k] : 0.f;
        }
        __syncthreads();
#pragma unroll
        for (int kk = 0; kk < 32; kk++) {
            float a0 = As[kk][ty * 2];
            float a1 = As[kk][ty * 2 + 1];
            float4 bv = *(const float4*)&Bs[kk][tx * 4];
            acc[0][0] += a0 * bv.x; acc[0][1] += a0 * bv.y;
            acc[0][2] += a0 * bv.z; acc[0][3] += a0 * bv.w;
            acc[1][0] += a1 * bv.x; acc[1][1] += a1 * bv.y;
            acc[1][2] += a1 * bv.z; acc[1][3] += a1 * bv.w;
        }
        __syncthreads();
    }
#pragma unroll
    for (int a = 0; a < 2; a++) {
        float4 v = make_float4(acc[a][0], acc[a][1], acc[a][2], acc[a][3]);
        *(float4*)&g_emb[(m0 + ty * 2 + a) * E_ + tx * 4] = v;
    }
}

// ---------------- K2: weight transposes ----------------
__global__ void k_transpose(const float* __restrict__ Whh_a,
                            const float* __restrict__ Whh_b,
                            const float* __restrict__ W_beta) {
    int idx = blockIdx.x * 256 + threadIdx.x;
    if (idx < E_ * NG) {
        int kk = idx / NG, c = idx % NG;
        g_WhhT[idx] = (c < G3) ? Whh_a[c * E_ + kk] : Whh_b[(c - G3) * E_ + kk];
    } else {
        idx -= E_ * NG;
        if (idx < E_ * E_) {
            int kk = idx / E_, e = idx % E_;
            g_WbetaT[idx] = W_beta[e * E_ + kk];
        }
    }
}

// ---------------- K3: GI = temb @ [Wih_a | Wih_b]^T + bih ----------------
// M=2048, N=768, K=129. BM=32, BN=64, 256 threads, each 2m x 4n.
__global__ void __launch_bounds__(256) k_gi(const float* __restrict__ tt,
                                            const float* __restrict__ Wih_a,
                                            const float* __restrict__ Wih_b,
                                            const float* __restrict__ bih_a,
                                            const float* __restrict__ bih_b) {
    __shared__ float As[64][33];   // [kk][m]
    __shared__ float Bs[64][68];   // [kk][n]
    const int m0  = blockIdx.x * 32;
    const int n0  = blockIdx.y * 64;
    const int tid = threadIdx.x;
    const int tx  = tid & 15;   // n = tx*4
    const int ty  = tid >> 4;   // m = ty*2
    float acc[2][4];
#pragma unroll
    for (int a = 0; a < 2; a++)
#pragma unroll
        for (int b = 0; b < 4; b++) acc[a][b] = 0.f;

    for (int k0 = 0; k0 < 129; k0 += 64) {
        for (int l = tid; l < 64 * 32; l += 256) {
            int kk = l & 63, mm = l >> 6;
            int k = k0 + kk;
            float v = 0.f;
            if (k < 128)       v = g_emb[(m0 + mm) * E_ + k];
            else if (k == 128) v = tt[m0 + mm];
            As[kk][mm] = v;
        }
        for (int l = tid; l < 64 * 64; l += 256) {
            int kk = l & 63, e = l >> 6;
            int k = k0 + kk;
            int g = n0 + e;
            float v = 0.f;
            if (k < 129)
                v = (g < G3) ? Wih_a[g * 129 + k] : Wih_b[(g - G3) * 129 + k];
            Bs[kk][e] = v;
        }
        __syncthreads();
#pragma unroll 8
        for (int kk = 0; kk < 64; kk++) {
            float a0 = As[kk][ty * 2];
            float a1 = As[kk][ty * 2 + 1];
            float4 bv = *(const float4*)&Bs[kk][tx * 4];
            acc[0][0] += a0 * bv.x; acc[0][1] += a0 * bv.y;
            acc[0][2] += a0 * bv.z; acc[0][3] += a0 * bv.w;
            acc[1][0] += a1 * bv.x; acc[1][1] += a1 * bv.y;
            acc[1][2] += a1 * bv.z; acc[1][3] += a1 * bv.w;
        }
        __syncthreads();
    }
#pragma unroll
    for (int a = 0; a < 2; a++)
#pragma unroll
        for (int b = 0; b < 4; b++) {
            int g = n0 + tx * 4 + b;
            float bih = (g < G3) ? bih_a[g] : bih_b[g - G3];
            g_GI[(m0 + ty * 2 + a) * NG + g] = acc[a][b] + bih;
        }
}

// ---------------- K4: fused GRU recurrence + online-softmax attention ----------------
// Block = (query pair {63-p, p}, 8 batch rows). 128 blocks, every block 65 steps.
// Softmax state + numerator live in registers of the owning warp (warp == row).
__global__ void __launch_bounds__(256) k_main(const int*   __restrict__ lengths,
                                              const float* __restrict__ bhh_a,
                                              const float* __restrict__ bhh_b,
                                              const float* __restrict__ w_alpha,
                                              const float* __restrict__ b_alpha,
                                              const float* __restrict__ b_beta,
                                              const float* __restrict__ W_out,
                                              const float* __restrict__ b_out,
                                              float* __restrict__ out) {
    __shared__ float sh_hT[2][E_][8];     // [gru][kk][row]
    __shared__ float sh_gh[8][NG];        // [row][gate-col]
    __shared__ float sh_bhh[NG];
    __shared__ float sh_wal[E_], sh_bbe[E_], sh_wout[E_];
    __shared__ float sh_balpha, sh_bout;

    const int tid   = threadIdx.x;
    const int pairp = blockIdx.x >> 2;    // 0..31
    const int bo    = blockIdx.x & 3;     // batches bo*8 .. bo*8+7

    for (int l = tid; l < NG; l += 256)
        sh_bhh[l] = (l < G3) ? bhh_a[l] : bhh_b[l - G3];
    if (tid < E_) {
        sh_wal[tid]  = w_alpha[tid];
        sh_bbe[tid]  = b_beta[tid];
        sh_wout[tid] = W_out[tid];
    }
    if (tid == 0) { sh_balpha = b_alpha[0]; sh_bout = b_out[0]; }

    const bool c1a = (tid + 256) < G3;    // 2nd gate column belongs to GRU-a?
    const int  row  = tid >> 5;           // warp's batch row (0..7)
    const int  lane = tid & 31;
    const int  bb   = bo * 8 + row;       // global batch index for this warp

    for (int seq = 0; seq < 2; seq++) {
        const int i = (seq == 0) ? (63 - pairp) : pairp;

        // reset state
        for (int l = tid; l < 2 * E_ * 8; l += 256) ((float*)sh_hT)[l] = 0.f;
        float m_run = -INFINITY, d_run = 0.f;     // lane-uniform softmax state
        float cacc[4] = {0.f, 0.f, 0.f, 0.f};     // numerator, e = lane + 32q
        __syncthreads();

        for (int k = 0; k <= i; k++) {
            const int j = i - k;          // source time index
            const int m = bb * T_ + j;

            // ---- phase 1: gh = h @ Whh^T (both GRUs), M=8, N=768, K=128
            {
                float acc0[8], acc1[8], acc2[8];
#pragma unroll
                for (int r = 0; r < 8; r++) { acc0[r] = 0.f; acc1[r] = 0.f; acc2[r] = 0.f; }
                const float* __restrict__ wp = g_WhhT + tid;
#pragma unroll 4
                for (int kk = 0; kk < E_; kk++) {
                    float w0 = wp[kk * NG];
                    float w1 = wp[kk * NG + 256];
                    float w2 = wp[kk * NG + 512];
                    float4 ha0 = *(const float4*)&sh_hT[0][kk][0];
                    float4 ha1 = *(const float4*)&sh_hT[0][kk][4];
                    float4 hb0 = *(const float4*)&sh_hT[1][kk][0];
                    float4 hb1 = *(const float4*)&sh_hT[1][kk][4];
                    float4 hm0 = c1a ? ha0 : hb0;
                    float4 hm1 = c1a ? ha1 : hb1;
                    acc0[0] += w0 * ha0.x; acc0[1] += w0 * ha0.y;
                    acc0[2] += w0 * ha0.z; acc0[3] += w0 * ha0.w;
                    acc0[4] += w0 * ha1.x; acc0[5] += w0 * ha1.y;
                    acc0[6] += w0 * ha1.z; acc0[7] += w0 * ha1.w;
                    acc1[0] += w1 * hm0.x; acc1[1] += w1 * hm0.y;
                    acc1[2] += w1 * hm0.z; acc1[3] += w1 * hm0.w;
                    acc1[4] += w1 * hm1.x; acc1[5] += w1 * hm1.y;
                    acc1[6] += w1 * hm1.z; acc1[7] += w1 * hm1.w;
                    acc2[0] += w2 * hb0.x; acc2[1] += w2 * hb0.y;
                    acc2[2] += w2 * hb0.z; acc2[3] += w2 * hb0.w;
                    acc2[4] += w2 * hb1.x; acc2[5] += w2 * hb1.y;
                    acc2[6] += w2 * hb1.z; acc2[7] += w2 * hb1.w;
                }
#pragma unroll
                for (int r = 0; r < 8; r++) {
                    sh_gh[r][tid]       = acc0[r];
                    sh_gh[r][tid + 256] = acc1[r];
                    sh_gh[r][tid + 512] = acc2[r];
                }
            }
            __syncthreads();

            // ---- phase 2: gate combine (gate order r,z,n)
#pragma unroll
            for (int u = 0; u < 8; u++) {
                int idx = tid + 256 * u;            // 0..2047
                int gru = idx >> 10;
                int rr  = (idx >> 7) & 7;
                int e   = idx & 127;
                int mm2 = (bo * 8 + rr) * T_ + j;
                int gb  = gru * G3;
                const float* __restrict__ gip = g_GI + mm2 * NG + gb + e;
                float gir = gip[0], giz = gip[128], gin = gip[256];
                float ghr = sh_gh[rr][gb + e]       + sh_bhh[gb + e];
                float ghz = sh_gh[rr][gb + 128 + e] + sh_bhh[gb + 128 + e];
                float ghn = sh_gh[rr][gb + 256 + e] + sh_bhh[gb + 256 + e];
                float rg = 1.f / (1.f + expf(-(gir + ghr)));
                float zg = 1.f / (1.f + expf(-(giz + ghz)));
                float ng = tanhf(gin + rg * ghn);
                float ho = sh_hT[gru][e][rr];
                sh_hT[gru][e][rr] = (1.f - zg) * ng + zg * ho;
            }
            __syncthreads();

            // ---- phase 3+4 (warp == row, registers only):
            // score -> online softmax update; beta GEMM; numerator update.
            {
                float p = 0.f;
#pragma unroll
                for (int q = 0; q < 4; q++) {
                    int e = lane + 32 * q;
                    p += sh_hT[0][e][row] * sh_wal[e];
                }
                p += __shfl_xor_sync(0xffffffffu, p, 16);
                p += __shfl_xor_sync(0xffffffffu, p, 8);
                p += __shfl_xor_sync(0xffffffffu, p, 4);
                p += __shfl_xor_sync(0xffffffffu, p, 2);
                p += __shfl_xor_sync(0xffffffffu, p, 1);
                float s  = p + sh_balpha;
                float mn = fmaxf(m_run, s);
                float sc = expf(m_run - mn);        // exp(-inf)=0 on first step
                float w  = expf(s - mn);
                d_run = d_run * sc + w;
                m_run = mn;

                float d0 = 0.f, d1 = 0.f, d2 = 0.f, d3 = 0.f;
#pragma unroll 4
                for (int kk = 0; kk < E_; kk++) {
                    float hv = sh_hT[1][kk][row];
                    const float* __restrict__ wbp = g_WbetaT + kk * E_ + lane;
                    d0 += hv * wbp[0];
                    d1 += hv * wbp[32];
                    d2 += hv * wbp[64];
                    d3 += hv * wbp[96];
                }
                float dd[4] = {d0, d1, d2, d3};
#pragma unroll
                for (int q = 0; q < 4; q++) {
                    int e = lane + 32 * q;
                    float beta = tanhf(dd[q] + sh_bbe[e]);
                    float er   = g_emb[m * E_ + e];
                    cacc[q] = cacc[q] * sc + w * beta * er;
                }
            }
            // no barrier here: next phase 1 only reads sh_hT (stable) and
            // overwrites sh_gh (dead after phase 2); the post-phase-1 barrier
            // orders phase-2's sh_hT writes against this phase's reads.
        }

        // ---- epilogue: c = cacc/d, length mask, out = c . W_out + b_out
        {
            float inv_d = 1.f / d_run;
            float p = 0.f;
#pragma unroll
            for (int q = 0; q < 4; q++) {
                int e = lane + 32 * q;
                p += (cacc[q] * inv_d) * sh_wout[e];
            }
            p += __shfl_xor_sync(0xffffffffu, p, 16);
            p += __shfl_xor_sync(0xffffffffu, p, 8);
            p += __shfl_xor_sync(0xffffffffu, p, 4);
            p += __shfl_xor_sync(0xffffffffu, p, 2);
            p += __shfl_xor_sync(0xffffffffu, p, 1);
            if (lane == 0) {
                float valid = (i < lengths[bb]) ? 1.f : 0.f;
                out[bb * T_ + i] = p * valid + sh_bout;
            }
        }
        __syncthreads();
    }
}

// ---------------- launch ----------------
extern "C" void kernel_launch(void* const* d_in, const int* in_sizes, int n_in,
                              void* d_out, int out_size) {
    const float* x       = (const float*)d_in[0];
    const float* tt      = (const float*)d_in[1];
    const int*   lengths = (const int*)  d_in[2];
    const float* Wemb    = (const float*)d_in[3];
    const float* Wih_a   = (const float*)d_in[4];
    const float* Whh_a   = (const float*)d_in[5];
    const float* bih_a   = (const float*)d_in[6];
    const float* bhh_a   = (const float*)d_in[7];
    const float* Wih_b   = (const float*)d_in[8];
    const float* Whh_b   = (const float*)d_in[9];
    const float* bih_b   = (const float*)d_in[10];
    const float* bhh_b   = (const float*)d_in[11];
    const float* w_alpha = (const float*)d_in[12];
    const float* b_alpha = (const float*)d_in[13];
    const float* W_beta  = (const float*)d_in[14];
    const float* b_beta  = (const float*)d_in[15];
    const float* W_out   = (const float*)d_in[16];
    const float* b_out   = (const float*)d_in[17];
    float* out = (float*)d_out;

    k_embed<<<128, 256>>>(x, Wemb);
    k_transpose<<<448, 256>>>(Whh_a, Whh_b, W_beta);
    k_gi<<<dim3(64, 12), 256>>>(tt, Wih_a, Wih_b, bih_a, bih_b);
    k_main<<<128, 256>>>(lengths, bhh_a, bhh_b, w_alpha, b_alpha,
                         b_beta, W_out, b_out, out);
}

// round 6
// speedup vs baseline: 1.8881x; 1.8881x over previous
#include <cuda_runtime.h>
#include <math.h>

#define B_   32
#define T_   64
#define BT   2048            // B*T
#define IND  4894
#define E_   128
#define G3   384             // 3*H
#define NG   768             // both GRUs' gates

#define WROWS_SMEM 44        // k-rows of Whh cached in smem
#define SMEM_DYN_FLOATS (E_*E_ + WROWS_SMEM*NG)   // 16384 + 33792 = 50176
#define SMEM_DYN_BYTES  (SMEM_DYN_FLOATS * 4)     // 200704 B

// ---------------- device scratch (no allocations allowed) ----------------
__device__ float g_emb[BT * E_];       // emb[m][e], m = b*T + t
__device__ float g_GI [BT * NG];       // input gates + bih (+ bhh for r,z)
__device__ float g_WhhT[E_ * NG];      // [kk][c], c = [Whh_a | Whh_b] cols
__device__ float g_WbetaT[E_ * E_];    // [kk][e]

__device__ __forceinline__ float fast_tanh(float x) {
    float y; asm("tanh.approx.f32 %0, %1;" : "=f"(y) : "f"(x)); return y;
}
__device__ __forceinline__ float fast_sigmoid(float x) {
    return 0.5f * fast_tanh(0.5f * x) + 0.5f;
}

// ---------------- K1: embedding GEMM  emb = x @ W_emb^T ----------------
__global__ void __launch_bounds__(256) k_embed(const float* __restrict__ x,
                                               const float* __restrict__ Wemb) {
    __shared__ float As[32][16];
    __shared__ float Bs[32][132];
    const int m0  = blockIdx.x * 16;
    const int tid = threadIdx.x;
    const int tx  = tid & 31;
    const int ty  = tid >> 5;
    float acc[2][4];
#pragma unroll
    for (int a = 0; a < 2; a++)
#pragma unroll
        for (int b = 0; b < 4; b++) acc[a][b] = 0.f;

    for (int k0 = 0; k0 < IND; k0 += 32) {
        for (int l = tid; l < 16 * 32; l += 256) {
            int kk = l & 31, mm = l >> 5;
            int k = k0 + kk;
            As[kk][mm] = (k < IND) ? x[(m0 + mm) * IND + k] : 0.f;
        }
        for (int l = tid; l < 128 * 32; l += 256) {
            int kk = l & 31, e = l >> 5;
            int k = k0 + kk;
            Bs[kk][e] = (k < IND) ? Wemb[e * IND + k] : 0.f;
        }
        __syncthreads();
#pragma unroll
        for (int kk = 0; kk < 32; kk++) {
            float a0 = As[kk][ty * 2];
            float a1 = As[kk][ty * 2 + 1];
            float4 bv = *(const float4*)&Bs[kk][tx * 4];
            acc[0][0] += a0 * bv.x; acc[0][1] += a0 * bv.y;
            acc[0][2] += a0 * bv.z; acc[0][3] += a0 * bv.w;
            acc[1][0] += a1 * bv.x; acc[1][1] += a1 * bv.y;
            acc[1][2] += a1 * bv.z; acc[1][3] += a1 * bv.w;
        }
        __syncthreads();
    }
#pragma unroll
    for (int a = 0; a < 2; a++) {
        float4 v = make_float4(acc[a][0], acc[a][1], acc[a][2], acc[a][3]);
        *(float4*)&g_emb[(m0 + ty * 2 + a) * E_ + tx * 4] = v;
    }
}

// ---------------- K2: weight transposes ----------------
__global__ void k_transpose(const float* __restrict__ Whh_a,
                            const float* __restrict__ Whh_b,
                            const float* __restrict__ W_beta) {
    int idx = blockIdx.x * 256 + threadIdx.x;
    if (idx < E_ * NG) {
        int kk = idx / NG, c = idx % NG;
        g_WhhT[idx] = (c < G3) ? Whh_a[c * E_ + kk] : Whh_b[(c - G3) * E_ + kk];
    } else {
        idx -= E_ * NG;
        if (idx < E_ * E_) {
            int kk = idx / E_, e = idx % E_;
            g_WbetaT[idx] = W_beta[e * E_ + kk];
        }
    }
}

// ---------------- K3: GI = temb @ [Wih_a | Wih_b]^T + bih (+bhh for r,z) ----
__global__ void __launch_bounds__(256) k_gi(const float* __restrict__ tt,
                                            const float* __restrict__ Wih_a,
                                            const float* __restrict__ Wih_b,
                                            const float* __restrict__ bih_a,
                                            const float* __restrict__ bih_b,
                                            const float* __restrict__ bhh_a,
                                            const float* __restrict__ bhh_b) {
    __shared__ float As[64][33];
    __shared__ float Bs[64][68];
    const int m0  = blockIdx.x * 32;
    const int n0  = blockIdx.y * 64;
    const int tid = threadIdx.x;
    const int tx  = tid & 15;
    const int ty  = tid >> 4;
    float acc[2][4];
#pragma unroll
    for (int a = 0; a < 2; a++)
#pragma unroll
        for (int b = 0; b < 4; b++) acc[a][b] = 0.f;

    for (int k0 = 0; k0 < 129; k0 += 64) {
        for (int l = tid; l < 64 * 32; l += 256) {
            int kk = l & 63, mm = l >> 6;
            int k = k0 + kk;
            float v = 0.f;
            if (k < 128)       v = g_emb[(m0 + mm) * E_ + k];
            else if (k == 128) v = tt[m0 + mm];
            As[kk][mm] = v;
        }
        for (int l = tid; l < 64 * 64; l += 256) {
            int kk = l & 63, e = l >> 6;
            int k = k0 + kk;
            int g = n0 + e;
            float v = 0.f;
            if (k < 129)
                v = (g < G3) ? Wih_a[g * 129 + k] : Wih_b[(g - G3) * 129 + k];
            Bs[kk][e] = v;
        }
        __syncthreads();
#pragma unroll 8
        for (int kk = 0; kk < 64; kk++) {
            float a0 = As[kk][ty * 2];
            float a1 = As[kk][ty * 2 + 1];
            float4 bv = *(const float4*)&Bs[kk][tx * 4];
            acc[0][0] += a0 * bv.x; acc[0][1] += a0 * bv.y;
            acc[0][2] += a0 * bv.z; acc[0][3] += a0 * bv.w;
            acc[1][0] += a1 * bv.x; acc[1][1] += a1 * bv.y;
            acc[1][2] += a1 * bv.z; acc[1][3] += a1 * bv.w;
        }
        __syncthreads();
    }
#pragma unroll
    for (int a = 0; a < 2; a++)
#pragma unroll
        for (int b = 0; b < 4; b++) {
            int g  = n0 + tx * 4 + b;
            int gg = (g < G3) ? g : g - G3;       // 0..383 within the GRU
            float bias = (g < G3) ? bih_a[gg] : bih_b[gg];
            if (gg < 256)                          // r and z gates: fold bhh too
                bias += (g < G3) ? bhh_a[gg] : bhh_b[gg];
            g_GI[(m0 + ty * 2 + a) * NG + g] = acc[a][b] + bias;
        }
}

// ---------------- K4: fused GRU recurrence + online-softmax attention --------
// Block = (query pair {63-p, p}, 8 batch rows). 128 blocks x 256 threads.
// Thread (gru = tid>>7, e = tid&127) owns gate triple (r,z,n)[e] for 8 rows:
// gate combine entirely in registers; h double-buffered -> 1 barrier/step.
__global__ void __launch_bounds__(256, 1)
k_main(const int*   __restrict__ lengths,
       const float* __restrict__ bhh_a,
       const float* __restrict__ bhh_b,
       const float* __restrict__ w_alpha,
       const float* __restrict__ b_alpha,
       const float* __restrict__ b_beta,
       const float* __restrict__ W_out,
       const float* __restrict__ b_out,
       float* __restrict__ out) {
    extern __shared__ float dynsm[];
    float* ws_beta = dynsm;                 // [128][128]
    float* ws_whh  = dynsm + E_ * E_;       // [WROWS_SMEM][768]

    __shared__ float sh_h[2][2][E_][8];     // [buf][gru][e][row]
    __shared__ float sh_wal[E_], sh_bbe[E_], sh_wout[E_];
    __shared__ float sh_balpha, sh_bout;

    const int tid   = threadIdx.x;
    const int pairp = blockIdx.x >> 2;      // 0..31
    const int bo    = blockIdx.x & 3;       // batches bo*8..bo*8+7
    const int gru   = tid >> 7;             // 0 = GRU-a, 1 = GRU-b
    const int e     = tid & 127;
    const int row   = tid >> 5;             // phase-D role: warp = batch row
    const int lane  = tid & 31;
    const int bb    = bo * 8 + row;
    const int cr    = gru * G3 + e;         // column of this thread's r-gate

    // cache W_beta^T and first WROWS_SMEM rows of Whh^T in smem
    {
        const float4* sb = (const float4*)g_WbetaT;
        float4* db = (float4*)ws_beta;
        for (int l = tid; l < E_ * E_ / 4; l += 256) db[l] = sb[l];
        const float4* sw = (const float4*)g_WhhT;   // rows 0..WROWS_SMEM-1 contiguous
        float4* dw = (float4*)ws_whh;
        for (int l = tid; l < WROWS_SMEM * NG / 4; l += 256) dw[l] = sw[l];
    }
    if (tid < E_) {
        sh_wal[tid]  = w_alpha[tid];
        sh_bbe[tid]  = b_beta[tid];
        sh_wout[tid] = W_out[tid];
    }
    if (tid == 0) { sh_balpha = b_alpha[0]; sh_bout = b_out[0]; }

    const float bhhn = gru ? bhh_b[256 + e] : bhh_a[256 + e];  // n-gate bhh stays separate

    for (int seq = 0; seq < 2; seq++) {
        const int i = seq ? pairp : (63 - pairp);

        // zero the "prev" buffer for k=0 (buf 1)
        for (int l = tid; l < 2 * E_ * 8; l += 256) ((float*)sh_h[1])[l] = 0.f;
        float m_run = -INFINITY, d_run = 0.f;
        float c0 = 0.f, c1 = 0.f, c2 = 0.f, c3 = 0.f;   // numerator, e = lane+32q
        __syncthreads();

        for (int k = 0; k <= i; k++) {
            const int j    = i - k;
            const int cur  = k & 1;
            const int prev = cur ^ 1;

            // ---- GI prefetch (independent of h -> hides L2 latency under GEMM)
            float gir[8], giz[8], gin[8];
            {
                const float* gp0 = g_GI + (bo * 8 * T_ + j) * NG + cr;
#pragma unroll
                for (int r = 0; r < 8; r++) {
                    const float* gp = gp0 + r * (T_ * NG);
                    gir[r] = gp[0]; giz[r] = gp[128]; gin[r] = gp[256];
                }
            }

            // ---- gh GEMM: acc{R,Z,N}[row] += w * h_prev[gru][kk][row]
            float aR[8], aZ[8], aN[8];
#pragma unroll
            for (int r = 0; r < 8; r++) { aR[r] = 0.f; aZ[r] = 0.f; aN[r] = 0.f; }
            const float* hp = &sh_h[prev][gru][0][0];   // [kk*8 + row]

#pragma unroll 4
            for (int kk = 0; kk < WROWS_SMEM; kk++) {   // smem-cached rows
                float wr = ws_whh[kk * NG + cr];
                float wz = ws_whh[kk * NG + cr + 128];
                float wn = ws_whh[kk * NG + cr + 256];
                float4 h0 = *(const float4*)(hp + kk * 8);
                float4 h1 = *(const float4*)(hp + kk * 8 + 4);
                aR[0] += wr * h0.x; aR[1] += wr * h0.y; aR[2] += wr * h0.z; aR[3] += wr * h0.w;
                aR[4] += wr * h1.x; aR[5] += wr * h1.y; aR[6] += wr * h1.z; aR[7] += wr * h1.w;
                aZ[0] += wz * h0.x; aZ[1] += wz * h0.y; aZ[2] += wz * h0.z; aZ[3] += wz * h0.w;
                aZ[4] += wz * h1.x; aZ[5] += wz * h1.y; aZ[6] += wz * h1.z; aZ[7] += wz * h1.w;
                aN[0] += wn * h0.x; aN[1] += wn * h0.y; aN[2] += wn * h0.z; aN[3] += wn * h0.w;
                aN[4] += wn * h1.x; aN[5] += wn * h1.y; aN[6] += wn * h1.z; aN[7] += wn * h1.w;
            }
            {
                const float* gw = g_WhhT + WROWS_SMEM * NG + cr;
#pragma unroll 4
                for (int kk = 0; kk < E_ - WROWS_SMEM; kk++) {  // L2-streamed rows
                    float wr = gw[kk * NG];
                    float wz = gw[kk * NG + 128];
                    float wn = gw[kk * NG + 256];
                    float4 h0 = *(const float4*)(hp + (WROWS_SMEM + kk) * 8);
                    float4 h1 = *(const float4*)(hp + (WROWS_SMEM + kk) * 8 + 4);
                    aR[0] += wr * h0.x; aR[1] += wr * h0.y; aR[2] += wr * h0.z; aR[3] += wr * h0.w;
                    aR[4] += wr * h1.x; aR[5] += wr * h1.y; aR[6] += wr * h1.z; aR[7] += wr * h1.w;
                    aZ[0] += wz * h0.x; aZ[1] += wz * h0.y; aZ[2] += wz * h0.z; aZ[3] += wz * h0.w;
                    aZ[4] += wz * h1.x; aZ[5] += wz * h1.y; aZ[6] += wz * h1.z; aZ[7] += wz * h1.w;
                    aN[0] += wn * h0.x; aN[1] += wn * h0.y; aN[2] += wn * h0.z; aN[3] += wn * h0.w;
                    aN[4] += wn * h1.x; aN[5] += wn * h1.y; aN[6] += wn * h1.z; aN[7] += wn * h1.w;
                }
            }

            // ---- gate combine in registers; write h_new to cur buffer
            {
                const float* hold = &sh_h[prev][gru][e][0];
                float4 ho0 = *(const float4*)(hold);
                float4 ho1 = *(const float4*)(hold + 4);
                float holda[8] = {ho0.x, ho0.y, ho0.z, ho0.w, ho1.x, ho1.y, ho1.z, ho1.w};
                float hn[8];
#pragma unroll
                for (int r = 0; r < 8; r++) {
                    float rg = fast_sigmoid(gir[r] + aR[r]);   // bhh_r folded in GI
                    float zg = fast_sigmoid(giz[r] + aZ[r]);   // bhh_z folded in GI
                    float ng = fast_tanh(gin[r] + rg * (aN[r] + bhhn));
                    hn[r] = (1.f - zg) * ng + zg * holda[r];
                }
                float* hw = &sh_h[cur][gru][e][0];
                *(float4*)hw       = make_float4(hn[0], hn[1], hn[2], hn[3]);
                *(float4*)(hw + 4) = make_float4(hn[4], hn[5], hn[6], hn[7]);
            }
            __syncthreads();

            // ---- phase D (warp = row): score, online softmax, beta, numerator
            {
                float p = 0.f;
#pragma unroll
                for (int q = 0; q < 4; q++) {
                    int ee = lane + 32 * q;
                    p += sh_h[cur][0][ee][row] * sh_wal[ee];
                }
                p += __shfl_xor_sync(0xffffffffu, p, 16);
                p += __shfl_xor_sync(0xffffffffu, p, 8);
                p += __shfl_xor_sync(0xffffffffu, p, 4);
                p += __shfl_xor_sync(0xffffffffu, p, 2);
                p += __shfl_xor_sync(0xffffffffu, p, 1);
                float s  = p + sh_balpha;
                float mn = fmaxf(m_run, s);
                float sc = __expf(m_run - mn);     // exp(-inf)=0 on first step
                float w  = __expf(s - mn);
                d_run = d_run * sc + w;
                m_run = mn;

                float d0 = 0.f, d1 = 0.f, d2 = 0.f, d3 = 0.f;
                const float* hb = &sh_h[cur][1][0][row];     // stride 8, broadcast
#pragma unroll 4
                for (int kk = 0; kk < E_; kk++) {
                    float hv = hb[kk * 8];
                    const float* wb = ws_beta + kk * E_ + lane;
                    d0 += hv * wb[0];
                    d1 += hv * wb[32];
                    d2 += hv * wb[64];
                    d3 += hv * wb[96];
                }
                const float* ep = g_emb + (bb * T_ + j) * E_ + lane;
                c0 = c0 * sc + w * fast_tanh(d0 + sh_bbe[lane])      * ep[0];
                c1 = c1 * sc + w * fast_tanh(d1 + sh_bbe[lane + 32]) * ep[32];
                c2 = c2 * sc + w * fast_tanh(d2 + sh_bbe[lane + 64]) * ep[64];
                c3 = c3 * sc + w * fast_tanh(d3 + sh_bbe[lane + 96]) * ep[96];
            }
            // no 2nd barrier: next step writes the other h buffer; all reads of
            // that buffer finished before this step's barrier.
        }

        // ---- epilogue: out = (num/d) . W_out * valid + b_out
        {
            float inv_d = 1.f / d_run;
            float p = c0 * sh_wout[lane]      + c1 * sh_wout[lane + 32]
                    + c2 * sh_wout[lane + 64] + c3 * sh_wout[lane + 96];
            p *= inv_d;
            p += __shfl_xor_sync(0xffffffffu, p, 16);
            p += __shfl_xor_sync(0xffffffffu, p, 8);
            p += __shfl_xor_sync(0xffffffffu, p, 4);
            p += __shfl_xor_sync(0xffffffffu, p, 2);
            p += __shfl_xor_sync(0xffffffffu, p, 1);
            if (lane == 0) {
                float valid = (i < lengths[bb]) ? 1.f : 0.f;
                out[bb * T_ + i] = p * valid + sh_bout;
            }
        }
        __syncthreads();
    }
}

// ---------------- launch ----------------
extern "C" void kernel_launch(void* const* d_in, const int* in_sizes, int n_in,
                              void* d_out, int out_size) {
    const float* x       = (const float*)d_in[0];
    const float* tt      = (const float*)d_in[1];
    const int*   lengths = (const int*)  d_in[2];
    const float* Wemb    = (const float*)d_in[3];
    const float* Wih_a   = (const float*)d_in[4];
    const float* Whh_a   = (const float*)d_in[5];
    const float* bih_a   = (const float*)d_in[6];
    const float* bhh_a   = (const float*)d_in[7];
    const float* Wih_b   = (const float*)d_in[8];
    const float* Whh_b   = (const float*)d_in[9];
    const float* bih_b   = (const float*)d_in[10];
    const float* bhh_b   = (const float*)d_in[11];
    const float* w_alpha = (const float*)d_in[12];
    const float* b_alpha = (const float*)d_in[13];
    const float* W_beta  = (const float*)d_in[14];
    const float* b_beta  = (const float*)d_in[15];
    const float* W_out   = (const float*)d_in[16];
    const float* b_out   = (const float*)d_in[17];
    float* out = (float*)d_out;

    // unconditional every call: deterministic, idempotent, not a stream op
    cudaFuncSetAttribute(k_main, cudaFuncAttributeMaxDynamicSharedMemorySize,
                         SMEM_DYN_BYTES);

    k_embed<<<128, 256>>>(x, Wemb);
    k_transpose<<<448, 256>>>(Whh_a, Whh_b, W_beta);
    k_gi<<<dim3(64, 12), 256>>>(tt, Wih_a, Wih_b, bih_a, bih_b, bhh_a, bhh_b);
    k_main<<<128, 256, SMEM_DYN_BYTES>>>(lengths, bhh_a, bhh_b, w_alpha, b_alpha,
                                         b_beta, W_out, b_out, out);
}